// round 9
// baseline (speedup 1.0000x reference)
#include <cuda_runtime.h>
#include <cuda_fp16.h>
#include <cstdint>
#include <math.h>

#define B_  4
#define T_  1024
#define E_  1024
#define H_  16
#define HS_ 64
#define D_  1024
#define V_  32000
#define BT_ 4096
#define QKV3 (3*D_)
#define PN_  (V_/32)        // LSE partials per row

// ---------------- scratch (device globals; no allocation allowed) ----------
__device__ __half g_hh[BT_*E_], g_hl[BT_*E_];          // embed split
__device__ float  g_qkv[BT_*QKV3];                      // q|k|v fp32
__device__ __half g_oh[BT_*D_], g_ol[BT_*D_];          // attn out split
__device__ __half g_fh[BT_*D_];                         // ff out hi only
__device__ __half g_wqkvh[QKV3*E_];                     // [n][k] hi only (2-pass)
__device__ __half g_wfh[D_*D_], g_wfl[D_*D_];
__device__ __half g_wch[V_*D_];                         // fc weights hi only
__device__ float  g_pm[(size_t)BT_*PN_], g_ps[(size_t)BT_*PN_];
__device__ float  g_loss[BT_];

// ---------------- FFMA-only exp (used ONLY in low-register contexts) --------
__device__ __forceinline__ float fast_exp(float x) {
    float y = fmaxf(x * 1.44269504f, -126.0f);
    float r = y + 12582912.0f;               // round-to-nearest-int trick
    int   n = __float_as_int(r) - 0x4B400000;
    float f = y - (r - 12582912.0f);         // frac in [-0.5, 0.5]
    float p =             1.33335581e-3f;
    p = fmaf(p, f, 9.61812911e-3f);
    p = fmaf(p, f, 5.55041087e-2f);
    p = fmaf(p, f, 2.40226507e-1f);
    p = fmaf(p, f, 6.93147181e-1f);
    p = fmaf(p, f, 1.0f);
    return p * __int_as_float((n + 127) << 23);
}

// ---------------- embedding: h = tok_emb[x] + pos_emb[t], split to fp16 -----
__global__ __launch_bounds__(256) void embed_split(const int* __restrict__ x,
                                                   const float* __restrict__ tok,
                                                   const float* __restrict__ pos) {
    int idx = blockIdx.x * 256 + threadIdx.x;
    int r = idx >> 8;
    int c = idx & 255;
    int token = x[r];
    int t = r & (T_ - 1);
    float4 a = ((const float4*)tok)[(size_t)token * 256 + c];
    float4 b = ((const float4*)pos)[(size_t)t * 256 + c];
    float v[4] = {a.x + b.x, a.y + b.y, a.z + b.z, a.w + b.w};
    __half h[4], l[4];
#pragma unroll
    for (int i = 0; i < 4; i++) {
        h[i] = __float2half(v[i]);
        l[i] = __float2half(v[i] - __half2float(h[i]));
    }
    ((__half2*)g_hh)[idx * 2 + 0] = __halves2half2(h[0], h[1]);
    ((__half2*)g_hh)[idx * 2 + 1] = __halves2half2(h[2], h[3]);
    ((__half2*)g_hl)[idx * 2 + 0] = __halves2half2(l[0], l[1]);
    ((__half2*)g_hl)[idx * 2 + 1] = __halves2half2(l[2], l[3]);
}

// ---------------- weight transpose + split: W[K][N] -> hi(/lo) [N][K] ------
template <int HEADB, int WLO>
__global__ __launch_bounds__(256) void wsplit(const float* __restrict__ W,
                                              __half* __restrict__ hi,
                                              __half* __restrict__ lo,
                                              int K, int N) {
    __shared__ float tile[32][33];
    int n0 = blockIdx.x * 32, k0 = blockIdx.y * 32;
    int tx = threadIdx.x & 31, ty = threadIdx.x >> 5;
#pragma unroll
    for (int j = 0; j < 4; j++) {
        int k = k0 + ty + j * 8, n = n0 + tx;
        float v = HEADB ? W[((size_t)(n >> 6) * K + k) * 64 + (n & 63)]
                        : W[(size_t)k * N + n];
        tile[ty + j * 8][tx] = v;
    }
    __syncthreads();
#pragma unroll
    for (int j = 0; j < 2; j++) {
        int idx = threadIdx.x + j * 256;      // 0..511
        int nl = idx >> 4;                    // 0..31
        int kc = idx & 15;                    // 0..15
        int n = n0 + nl, k = k0 + kc * 2;
        float v0 = tile[kc * 2][nl], v1 = tile[kc * 2 + 1][nl];
        __half h0 = __float2half(v0), h1 = __float2half(v1);
        *(__half2*)(hi + (size_t)n * K + k) = __halves2half2(h0, h1);
        if (WLO) {
            *(__half2*)(lo + (size_t)n * K + k) = __halves2half2(
                __float2half(v0 - __half2float(h0)),
                __float2half(v1 - __half2float(h1)));
        }
    }
}

// ---------------- split-fp16 tensor-core GEMM -------------------------------
// NP=3: ah*bh + ah*bl + al*bh ; NP=2: ah*bh + al*bh ; NP=1: ah*bh
// OUTMODE: 0 = fp32 C, 1 = half hi+lo, 2 = half hi only
#define SSTR 40
#define ATILE (128*SSTR)

__device__ __forceinline__ void cpa16(uint32_t dst, const void* src) {
    asm volatile("cp.async.cg.shared.global [%0], [%1], 16;\n" :: "r"(dst), "l"(src));
}
#define LDM4(R, ADDR) \
    asm volatile("ldmatrix.sync.aligned.m8n8.x4.shared.b16 {%0,%1,%2,%3}, [%4];" \
        : "=r"(R[0]), "=r"(R[1]), "=r"(R[2]), "=r"(R[3]) : "r"(ADDR))
#define MMAF16(Cc, Aa, B0, B1) \
    asm volatile("mma.sync.aligned.m16n8k16.row.col.f32.f16.f16.f32 " \
        "{%0,%1,%2,%3}, {%4,%5,%6,%7}, {%8,%9}, {%0,%1,%2,%3};" \
        : "+f"(Cc[0]), "+f"(Cc[1]), "+f"(Cc[2]), "+f"(Cc[3]) \
        : "r"(Aa[0]), "r"(Aa[1]), "r"(Aa[2]), "r"(Aa[3]), "r"(B0), "r"(B1))

template <int NP, int HASBIAS, int RELU, int OUTMODE, int LSE>
__global__ __launch_bounds__(256) void mma_gemm(
    const __half* __restrict__ Ah, const __half* __restrict__ Al,
    const __half* __restrict__ Bh, const __half* __restrict__ Bl,
    const float* __restrict__ bias, float* __restrict__ C,
    __half* __restrict__ Ch, __half* __restrict__ Cl,
    int M, int N, int K)
{
    extern __shared__ __half sm[];
    constexpr int NA   = (NP >= 2) ? 2 : 1;
    constexpr int NB   = (NP == 3) ? 2 : 1;
    constexpr int NARR = NA + NB;
    constexpr int STG  = NARR * ATILE;
    const int m0 = blockIdx.x * 128, n0 = blockIdx.y * 128;   // rows fastest
    const int tid = threadIdx.x;
    const int lane = tid & 31, w = tid >> 5;
    const int wm = w >> 2, wn = w & 3;
    const uint32_t smb = (uint32_t)__cvta_generic_to_shared(sm);

    const int nk = K >> 5;

    auto load_stage = [&](int s, int k0) {
#pragma unroll
        for (int i = 0; i < 2 * NARR; i++) {
            const int arr = i >> 1;
            int rem = ((i & 1) << 8) + tid;
            int row = rem >> 2, seg = tid & 3;
            const __half* gp = (arr < NA) ? ((arr == 0) ? Ah : Al)
                                          : ((arr == NA) ? Bh : Bl);
            int grow = ((arr < NA) ? m0 : n0) + row;
            const __half* src = gp + (size_t)grow * K + k0 + seg * 8;
            uint32_t dst = smb + (uint32_t)((s * STG + arr * ATILE + row * SSTR + seg * 8) << 1);
            cpa16(dst, src);
        }
        asm volatile("cp.async.commit_group;\n" ::: "memory");
    };

    load_stage(0, 0);
    load_stage(1, 32);

    float acc[4][4][4];
#pragma unroll
    for (int a = 0; a < 4; a++)
#pragma unroll
        for (int b = 0; b < 4; b++)
#pragma unroll
            for (int c = 0; c < 4; c++) acc[a][b][c] = 0.f;

    const int t8 = lane >> 3, r8 = lane & 7;

    for (int kt = 0; kt < nk; kt++) {
        asm volatile("cp.async.wait_group 1;\n" ::: "memory");
        __syncthreads();
        const uint32_t base = smb + (uint32_t)(((kt & 1) * STG) << 1);
#pragma unroll
        for (int kk = 0; kk < 2; kk++) {
            const int kof = kk << 4;
            uint32_t ah[4][4], al[4][4], bh[2][4], bl[2][4];
#pragma unroll
            for (int mt = 0; mt < 4; mt++) {
                int mrow = wm * 64 + mt * 16 + ((t8 & 1) << 3) + r8;
                int kcol = kof + ((t8 >> 1) << 3);
                uint32_t ad = base + (uint32_t)((mrow * SSTR + kcol) << 1);
                LDM4(ah[mt], ad);
                if (NP >= 2) LDM4(al[mt], ad + (ATILE << 1));
            }
#pragma unroll
            for (int np = 0; np < 2; np++) {
                int nrow = wn * 32 + np * 16 + ((t8 >> 1) << 3) + r8;
                int kcol = kof + ((t8 & 1) << 3);
                uint32_t bd = base + (uint32_t)((NA * ATILE + nrow * SSTR + kcol) << 1);
                LDM4(bh[np], bd);
                if (NP == 3) LDM4(bl[np], bd + (ATILE << 1));
            }
#pragma unroll
            for (int mt = 0; mt < 4; mt++)
#pragma unroll
                for (int np = 0; np < 2; np++)
#pragma unroll
                    for (int hf = 0; hf < 2; hf++) {
                        float* cc = acc[mt][np * 2 + hf];
                        MMAF16(cc, ah[mt], bh[np][hf * 2], bh[np][hf * 2 + 1]);
                        if (NP >= 2)
                            MMAF16(cc, al[mt], bh[np][hf * 2], bh[np][hf * 2 + 1]);
                        if (NP == 3)
                            MMAF16(cc, ah[mt], bl[np][hf * 2], bl[np][hf * 2 + 1]);
                    }
        }
        __syncthreads();
        if (kt + 2 < nk) load_stage(kt & 1, (kt + 2) << 5);
        else asm volatile("cp.async.commit_group;\n" ::: "memory");
    }

    // ---------------- epilogue ----------------
    float bj[8];
#pragma unroll
    for (int nt = 0; nt < 4; nt++) {
        int col = n0 + wn * 32 + nt * 8 + ((lane & 3) << 1);
        bj[nt * 2 + 0] = HASBIAS ? bias[col] : 0.f;
        bj[nt * 2 + 1] = HASBIAS ? bias[col + 1] : 0.f;
    }
#pragma unroll
    for (int mt = 0; mt < 4; mt++) {
#pragma unroll
        for (int hf = 0; hf < 2; hf++) {
            int row = m0 + wm * 64 + mt * 16 + (lane >> 2) + hf * 8;
            float vv[8];
            float vmax = -INFINITY;
#pragma unroll
            for (int nt = 0; nt < 4; nt++) {
#pragma unroll
                for (int j = 0; j < 2; j++) {
                    float v = acc[mt][nt][hf * 2 + j] + bj[nt * 2 + j];
                    if (RELU) v = fmaxf(v, 0.f);
                    vv[nt * 2 + j] = v;
                    vmax = fmaxf(vmax, v);
                }
            }
#pragma unroll
            for (int nt = 0; nt < 4; nt++) {
                int col = n0 + wn * 32 + nt * 8 + ((lane & 3) << 1);
                if (OUTMODE == 1) {
                    __half h0 = __float2half(vv[nt * 2]);
                    __half h1 = __float2half(vv[nt * 2 + 1]);
                    *(__half2*)(Ch + (size_t)row * N + col) = __halves2half2(h0, h1);
                    *(__half2*)(Cl + (size_t)row * N + col) = __halves2half2(
                        __float2half(vv[nt * 2] - __half2float(h0)),
                        __float2half(vv[nt * 2 + 1] - __half2float(h1)));
                } else if (OUTMODE == 2) {
                    *(__half2*)(Ch + (size_t)row * N + col) = __halves2half2(
                        __float2half(vv[nt * 2]), __float2half(vv[nt * 2 + 1]));
                } else {
                    float2 o; o.x = vv[nt * 2]; o.y = vv[nt * 2 + 1];
                    *(float2*)(C + (size_t)row * N + col) = o;
                }
            }
            if (LSE) {
                float rs = 0.f;
#pragma unroll
                for (int k = 0; k < 8; k++) rs += fast_exp(vv[k] - vmax);
                float rm = vmax;
#pragma unroll
                for (int off = 1; off <= 2; off <<= 1) {
                    float m2 = __shfl_xor_sync(0xFFFFFFFFu, rm, off);
                    float s2 = __shfl_xor_sync(0xFFFFFFFFu, rs, off);
                    float mn = fmaxf(rm, m2);
                    rs = rs * fast_exp(rm - mn) + s2 * fast_exp(m2 - mn);
                    rm = mn;
                }
                if ((lane & 3) == 0) {
                    int pcol = blockIdx.y * 4 + wn;
                    g_pm[(size_t)row * PN_ + pcol] = rm;
                    g_ps[(size_t)row * PN_ + pcol] = rs;
                }
            }
        }
    }
}

// ---------------- causal attention (fp32, online softmax) -------------------
__global__ __launch_bounds__(128) void attn_kernel() {
    __shared__ float kv[64][64];
    __shared__ float sc[64][128];
    const int z   = blockIdx.y;
    const int b   = z >> 4;
    const int hh  = z & 15;
    const int tid = threadIdx.x;
    const int bx  = gridDim.x - 1 - blockIdx.x;    // heavy tiles first
    const int t   = bx * 128 + tid;

    const float4* qp = (const float4*)(g_qkv + (size_t)(b * T_ + t) * QKV3 + hh * HS_);
    float q[64];
#pragma unroll
    for (int d4 = 0; d4 < 16; d4++) {
        float4 qq = qp[d4];
        q[d4 * 4 + 0] = qq.x * 8.0f;    // * sqrt(HS)
        q[d4 * 4 + 1] = qq.y * 8.0f;
        q[d4 * 4 + 2] = qq.z * 8.0f;
        q[d4 * 4 + 3] = qq.w * 8.0f;
    }

    float acc[64];
#pragma unroll
    for (int d = 0; d < 64; d++) acc[d] = 0.f;
    float m = -INFINITY, l = 0.f;

    const int smax = bx * 128 + 127;
    for (int s0 = 0; s0 <= smax; s0 += 64) {
        const float* kbase = g_qkv + (size_t)(b * T_ + s0) * QKV3 + D_ + hh * HS_;
#pragma unroll
        for (int i = 0; i < 8; i++) {
            int lin = tid + 128 * i;
            int row = lin >> 4, c4 = lin & 15;
            *(float4*)&kv[row][c4 * 4] =
                *(const float4*)(kbase + (size_t)row * QKV3 + c4 * 4);
        }
        __syncthreads();

        int cnt = t - s0 + 1;
        cnt = cnt < 0 ? 0 : (cnt > 64 ? 64 : cnt);
        for (int j = 0; j < cnt; j++) {
            const float4* kr = (const float4*)kv[j];
            float p0 = 0.f, p1 = 0.f, p2 = 0.f, p3 = 0.f;
#pragma unroll
            for (int d4 = 0; d4 < 16; d4++) {
                float4 kk = kr[d4];
                p0 = fmaf(q[d4 * 4 + 0], kk.x, p0);
                p1 = fmaf(q[d4 * 4 + 1], kk.y, p1);
                p2 = fmaf(q[d4 * 4 + 2], kk.z, p2);
                p3 = fmaf(q[d4 * 4 + 3], kk.w, p3);
            }
            sc[j][tid] = (p0 + p1) + (p2 + p3);
        }
        __syncthreads();

        const float* vbase = g_qkv + (size_t)(b * T_ + s0) * QKV3 + 2 * D_ + hh * HS_;
#pragma unroll
        for (int i = 0; i < 8; i++) {
            int lin = tid + 128 * i;
            int row = lin >> 4, c4 = lin & 15;
            *(float4*)&kv[row][c4 * 4] =
                *(const float4*)(vbase + (size_t)row * QKV3 + c4 * 4);
        }
        __syncthreads();

        if (cnt > 0) {
            float t0 = -INFINITY, t1 = -INFINITY, t2 = -INFINITY, t3 = -INFINITY;
            int j = 0;
            for (; j + 3 < cnt; j += 4) {
                t0 = fmaxf(t0, sc[j][tid]);
                t1 = fmaxf(t1, sc[j + 1][tid]);
                t2 = fmaxf(t2, sc[j + 2][tid]);
                t3 = fmaxf(t3, sc[j + 3][tid]);
            }
            for (; j < cnt; j++) t0 = fmaxf(t0, sc[j][tid]);
            float tmax = fmaxf(fmaxf(t0, t1), fmaxf(t2, t3));
            float mn = fmaxf(m, tmax);
            float scale = __expf(m - mn);
            l *= scale;
#pragma unroll
            for (int d = 0; d < 64; d++) acc[d] *= scale;
            for (j = 0; j < cnt; j++) {
                float p = __expf(sc[j][tid] - mn);
                l += p;
                const float4* vr = (const float4*)kv[j];
#pragma unroll
                for (int d4 = 0; d4 < 16; d4++) {
                    float4 vv4 = vr[d4];
                    acc[d4 * 4 + 0] = fmaf(p, vv4.x, acc[d4 * 4 + 0]);
                    acc[d4 * 4 + 1] = fmaf(p, vv4.y, acc[d4 * 4 + 1]);
                    acc[d4 * 4 + 2] = fmaf(p, vv4.z, acc[d4 * 4 + 2]);
                    acc[d4 * 4 + 3] = fmaf(p, vv4.w, acc[d4 * 4 + 3]);
                }
            }
            m = mn;
        }
        __syncthreads();
    }

    float inv = 1.f / l;
    size_t obase = (size_t)(b * T_ + t) * D_ + hh * HS_;
#pragma unroll
    for (int d = 0; d < 64; d++) {
        float v = acc[d] * inv;
        __half hv = __float2half(v);
        g_oh[obase + d] = hv;
        g_ol[obase + d] = __float2half(v - __half2float(hv));
    }
}

// ---------------- loss from LSE partials -------------------------------------
__global__ __launch_bounds__(256) void loss_partial_kernel(const float* __restrict__ logits,
                                                           const int* __restrict__ y) {
    __shared__ float sm_m[256], sm_s[256];
    int row = blockIdx.x;
    int tid = threadIdx.x;
    float m = -INFINITY, s = 0.f;
    for (int i = tid; i < PN_; i += 256) {
        float m2 = g_pm[(size_t)row * PN_ + i];
        float s2 = g_ps[(size_t)row * PN_ + i];
        float mn = fmaxf(m, m2);
        s = s * fast_exp(m - mn) + s2 * fast_exp(m2 - mn);
        m = mn;
    }
    sm_m[tid] = m; sm_s[tid] = s;
    __syncthreads();
    for (int k = 128; k > 0; k >>= 1) {
        if (tid < k) {
            float m2 = sm_m[tid + k], s2 = sm_s[tid + k];
            float mn = fmaxf(sm_m[tid], m2);
            sm_s[tid] = sm_s[tid] * fast_exp(sm_m[tid] - mn) + s2 * fast_exp(m2 - mn);
            sm_m[tid] = mn;
        }
        __syncthreads();
    }
    if (tid == 0) {
        g_loss[row] = sm_m[0] + logf(sm_s[0]) - logits[(size_t)row * V_ + y[row]];
    }
}

__global__ __launch_bounds__(256) void loss_mean_kernel(float* out) {
    __shared__ float red[256];
    int tid = threadIdx.x;
    float s = 0.f;
    for (int i = tid; i < BT_; i += 256) s += g_loss[i];
    red[tid] = s;
    __syncthreads();
    for (int k = 128; k > 0; k >>= 1) {
        if (tid < k) red[tid] += red[tid + k];
        __syncthreads();
    }
    if (tid == 0) *out = red[0] / (float)BT_;
}

// ---------------- launch ----------------------------------------------------
extern "C" void kernel_launch(void* const* d_in, const int* in_sizes, int n_in,
                              void* d_out, int out_size) {
    const int*   x   = (const int*)d_in[0];
    const int*   y   = (const int*)d_in[1];
    const float* tok = (const float*)d_in[2];
    const float* pos = (const float*)d_in[3];
    const float* Wq  = (const float*)d_in[4];
    const float* Wk  = (const float*)d_in[5];
    const float* Wv  = (const float*)d_in[6];
    const float* ffw = (const float*)d_in[7];
    const float* ffb = (const float*)d_in[8];
    const float* fcw = (const float*)d_in[9];
    const float* fcb = (const float*)d_in[10];
    float* out = (float*)d_out;

    __half *phh, *phl, *poh, *pol, *pfh;
    __half *pwqh, *pwfh, *pwfl, *pwch;
    float *pqkv;
    cudaGetSymbolAddress((void**)&phh, g_hh);
    cudaGetSymbolAddress((void**)&phl, g_hl);
    cudaGetSymbolAddress((void**)&poh, g_oh);
    cudaGetSymbolAddress((void**)&pol, g_ol);
    cudaGetSymbolAddress((void**)&pfh, g_fh);
    cudaGetSymbolAddress((void**)&pwqh, g_wqkvh);
    cudaGetSymbolAddress((void**)&pwfh, g_wfh);
    cudaGetSymbolAddress((void**)&pwfl, g_wfl);
    cudaGetSymbolAddress((void**)&pwch, g_wch);
    cudaGetSymbolAddress((void**)&pqkv, g_qkv);

    const int smem3 = 2 * 4 * ATILE * 2;   // 81920 B (Ah,Al,Bh,Bl x2)
    const int smem2 = 2 * 3 * ATILE * 2;   // 61440 B (Ah,Al,Bh x2)
    const int smem1 = 2 * 2 * ATILE * 2;   // 40960 B (Ah,Bh x2)
    cudaFuncSetAttribute(mma_gemm<2,0,0,0,0>, cudaFuncAttributeMaxDynamicSharedMemorySize, smem2);
    cudaFuncSetAttribute(mma_gemm<3,1,1,2,0>, cudaFuncAttributeMaxDynamicSharedMemorySize, smem3);
    cudaFuncSetAttribute(mma_gemm<1,1,0,0,1>, cudaFuncAttributeMaxDynamicSharedMemorySize, smem1);

    // launch order chosen so attn_kernel is the 6th launch (ncu -s 5 -c 1)
    embed_split<<<(BT_ * E_ / 4) / 256, 256>>>(x, tok, pos);                       // 1
    wsplit<1,0><<<dim3(D_/32, E_/32), 256>>>(Wq, pwqh,           nullptr, E_, D_); // 2
    wsplit<1,0><<<dim3(D_/32, E_/32), 256>>>(Wk, pwqh + D_*E_,   nullptr, E_, D_); // 3
    wsplit<1,0><<<dim3(D_/32, E_/32), 256>>>(Wv, pwqh + 2*D_*E_, nullptr, E_, D_); // 4
    mma_gemm<2,0,0,0,0><<<dim3(BT_/128, QKV3/128), 256, smem2>>>(                  // 5
        phh, phl, pwqh, nullptr, nullptr, pqkv, nullptr, nullptr, BT_, QKV3, E_);
    attn_kernel<<<dim3(T_/128, B_*H_), 128>>>();                                   // 6
    wsplit<0,1><<<dim3(D_/32, D_/32), 256>>>(ffw, pwfh, pwfl, D_, D_);             // 7
    mma_gemm<3,1,1,2,0><<<dim3(BT_/128, D_/128), 256, smem3>>>(                    // 8
        poh, pol, pwfh, pwfl, ffb, nullptr, pfh, nullptr, BT_, D_, D_);
    wsplit<0,0><<<dim3(V_/32, D_/32), 256>>>(fcw, pwch, nullptr, D_, V_);          // 9
    mma_gemm<1,1,0,0,1><<<dim3(BT_/128, V_/128), 256, smem1>>>(                    // 10
        pfh, nullptr, pwch, nullptr, fcb, out, nullptr, nullptr, BT_, V_, D_);
    loss_partial_kernel<<<BT_, 256>>>(out, y);                                     // 11
    long long logits_elems = (long long)BT_ * V_;
    if ((long long)out_size > logits_elems) {
        loss_mean_kernel<<<1, 256>>>(out + (size_t)logits_elems);                  // 12
    }
}

// round 10
// speedup vs baseline: 1.0912x; 1.0912x over previous
#include <cuda_runtime.h>
#include <cuda_fp16.h>
#include <cstdint>
#include <math.h>

#define B_  4
#define T_  1024
#define E_  1024
#define H_  16
#define HS_ 64
#define D_  1024
#define V_  32000
#define BT_ 4096
#define QKV3 (3*D_)
#define PN_  (V_/32)        // LSE partials per row

// ---------------- scratch (device globals; no allocation allowed) ----------
__device__ __half g_hh[BT_*E_], g_hl[BT_*E_];          // embed split
__device__ float  g_qkv[BT_*QKV3];                      // q|k|v fp32
__device__ __half g_oh[BT_*D_], g_ol[BT_*D_];          // attn out split
__device__ __half g_fh[BT_*D_];                         // ff out hi only
__device__ __half g_wqkvh[QKV3*E_];                     // [n][k] hi only (2-pass)
__device__ __half g_wfh[D_*D_], g_wfl[D_*D_];
__device__ __half g_wch[V_*D_];                         // fc weights hi only
__device__ float  g_pm[(size_t)BT_*PN_], g_ps[(size_t)BT_*PN_];
__device__ float  g_loss[BT_];

// ---------------- FFMA-only exp (used ONLY in low-register contexts) --------
__device__ __forceinline__ float fast_exp(float x) {
    float y = fmaxf(x * 1.44269504f, -126.0f);
    float r = y + 12582912.0f;               // round-to-nearest-int trick
    int   n = __float_as_int(r) - 0x4B400000;
    float f = y - (r - 12582912.0f);         // frac in [-0.5, 0.5]
    float p =             1.33335581e-3f;
    p = fmaf(p, f, 9.61812911e-3f);
    p = fmaf(p, f, 5.55041087e-2f);
    p = fmaf(p, f, 2.40226507e-1f);
    p = fmaf(p, f, 6.93147181e-1f);
    p = fmaf(p, f, 1.0f);
    return p * __int_as_float((n + 127) << 23);
}

// ---------------- embedding: h = tok_emb[x] + pos_emb[t], split to fp16 -----
__global__ __launch_bounds__(256) void embed_split(const int* __restrict__ x,
                                                   const float* __restrict__ tok,
                                                   const float* __restrict__ pos) {
    int idx = blockIdx.x * 256 + threadIdx.x;
    int r = idx >> 8;
    int c = idx & 255;
    int token = x[r];
    int t = r & (T_ - 1);
    float4 a = ((const float4*)tok)[(size_t)token * 256 + c];
    float4 b = ((const float4*)pos)[(size_t)t * 256 + c];
    float v[4] = {a.x + b.x, a.y + b.y, a.z + b.z, a.w + b.w};
    __half h[4], l[4];
#pragma unroll
    for (int i = 0; i < 4; i++) {
        h[i] = __float2half(v[i]);
        l[i] = __float2half(v[i] - __half2float(h[i]));
    }
    ((__half2*)g_hh)[idx * 2 + 0] = __halves2half2(h[0], h[1]);
    ((__half2*)g_hh)[idx * 2 + 1] = __halves2half2(h[2], h[3]);
    ((__half2*)g_hl)[idx * 2 + 0] = __halves2half2(l[0], l[1]);
    ((__half2*)g_hl)[idx * 2 + 1] = __halves2half2(l[2], l[3]);
}

// ---------------- weight transpose + split: W[K][N] -> hi(/lo) [N][K] ------
template <int HEADB, int WLO>
__global__ __launch_bounds__(256) void wsplit(const float* __restrict__ W,
                                              __half* __restrict__ hi,
                                              __half* __restrict__ lo,
                                              int K, int N) {
    __shared__ float tile[32][33];
    int n0 = blockIdx.x * 32, k0 = blockIdx.y * 32;
    int tx = threadIdx.x & 31, ty = threadIdx.x >> 5;
#pragma unroll
    for (int j = 0; j < 4; j++) {
        int k = k0 + ty + j * 8, n = n0 + tx;
        float v = HEADB ? W[((size_t)(n >> 6) * K + k) * 64 + (n & 63)]
                        : W[(size_t)k * N + n];
        tile[ty + j * 8][tx] = v;
    }
    __syncthreads();
#pragma unroll
    for (int j = 0; j < 4; j++) {
        int n = n0 + ty + j * 8, k = k0 + tx;
        float v = tile[tx][ty + j * 8];
        __half h = __float2half(v);
        hi[(size_t)n * K + k] = h;
        if (WLO) lo[(size_t)n * K + k] = __float2half(v - __half2float(h));
    }
}

// ---------------- split-fp16 tensor-core GEMM -------------------------------
// NP=3: ah*bh + ah*bl + al*bh ; NP=2: ah*bh + al*bh ; NP=1: ah*bh
// OUTMODE: 0 = fp32 C, 1 = half hi+lo, 2 = half hi only
#define SSTR 40
#define ATILE (128*SSTR)

__device__ __forceinline__ void cpa16(uint32_t dst, const void* src) {
    asm volatile("cp.async.cg.shared.global [%0], [%1], 16;\n" :: "r"(dst), "l"(src));
}
#define LDM4(R, ADDR) \
    asm volatile("ldmatrix.sync.aligned.m8n8.x4.shared.b16 {%0,%1,%2,%3}, [%4];" \
        : "=r"(R[0]), "=r"(R[1]), "=r"(R[2]), "=r"(R[3]) : "r"(ADDR))
#define MMAF16(Cc, Aa, B0, B1) \
    asm volatile("mma.sync.aligned.m16n8k16.row.col.f32.f16.f16.f32 " \
        "{%0,%1,%2,%3}, {%4,%5,%6,%7}, {%8,%9}, {%0,%1,%2,%3};" \
        : "+f"(Cc[0]), "+f"(Cc[1]), "+f"(Cc[2]), "+f"(Cc[3]) \
        : "r"(Aa[0]), "r"(Aa[1]), "r"(Aa[2]), "r"(Aa[3]), "r"(B0), "r"(B1))

template <int NP, int HASBIAS, int RELU, int OUTMODE, int LSE>
__global__ __launch_bounds__(256) void mma_gemm(
    const __half* __restrict__ Ah, const __half* __restrict__ Al,
    const __half* __restrict__ Bh, const __half* __restrict__ Bl,
    const float* __restrict__ bias, float* __restrict__ C,
    __half* __restrict__ Ch, __half* __restrict__ Cl,
    int M, int N, int K)
{
    extern __shared__ __half sm[];
    constexpr int NA   = (NP >= 2) ? 2 : 1;
    constexpr int NB   = (NP == 3) ? 2 : 1;
    constexpr int NARR = NA + NB;
    constexpr int STG  = NARR * ATILE;
    const int m0 = blockIdx.x * 128, n0 = blockIdx.y * 128;   // rows fastest
    const int tid = threadIdx.x;
    const int lane = tid & 31, w = tid >> 5;
    const int wm = w >> 2, wn = w & 3;
    const uint32_t smb = (uint32_t)__cvta_generic_to_shared(sm);

    const int nk = K >> 5;

    auto load_stage = [&](int s, int k0) {
#pragma unroll
        for (int i = 0; i < 2 * NARR; i++) {
            const int arr = i >> 1;
            int rem = ((i & 1) << 8) + tid;
            int row = rem >> 2, seg = tid & 3;
            const __half* gp = (arr < NA) ? ((arr == 0) ? Ah : Al)
                                          : ((arr == NA) ? Bh : Bl);
            int grow = ((arr < NA) ? m0 : n0) + row;
            const __half* src = gp + (size_t)grow * K + k0 + seg * 8;
            uint32_t dst = smb + (uint32_t)((s * STG + arr * ATILE + row * SSTR + seg * 8) << 1);
            cpa16(dst, src);
        }
        asm volatile("cp.async.commit_group;\n" ::: "memory");
    };

    load_stage(0, 0);
    load_stage(1, 32);

    float acc[4][4][4];
#pragma unroll
    for (int a = 0; a < 4; a++)
#pragma unroll
        for (int b = 0; b < 4; b++)
#pragma unroll
            for (int c = 0; c < 4; c++) acc[a][b][c] = 0.f;

    const int t8 = lane >> 3, r8 = lane & 7;

    for (int kt = 0; kt < nk; kt++) {
        asm volatile("cp.async.wait_group 1;\n" ::: "memory");
        __syncthreads();
        const uint32_t base = smb + (uint32_t)(((kt & 1) * STG) << 1);
#pragma unroll
        for (int kk = 0; kk < 2; kk++) {
            const int kof = kk << 4;
            uint32_t ah[4][4], al[4][4], bh[2][4], bl[2][4];
#pragma unroll
            for (int mt = 0; mt < 4; mt++) {
                int mrow = wm * 64 + mt * 16 + ((t8 & 1) << 3) + r8;
                int kcol = kof + ((t8 >> 1) << 3);
                uint32_t ad = base + (uint32_t)((mrow * SSTR + kcol) << 1);
                LDM4(ah[mt], ad);
                if (NP >= 2) LDM4(al[mt], ad + (ATILE << 1));
            }
#pragma unroll
            for (int np = 0; np < 2; np++) {
                int nrow = wn * 32 + np * 16 + ((t8 >> 1) << 3) + r8;
                int kcol = kof + ((t8 & 1) << 3);
                uint32_t bd = base + (uint32_t)((NA * ATILE + nrow * SSTR + kcol) << 1);
                LDM4(bh[np], bd);
                if (NP == 3) LDM4(bl[np], bd + (ATILE << 1));
            }
#pragma unroll
            for (int mt = 0; mt < 4; mt++)
#pragma unroll
                for (int np = 0; np < 2; np++)
#pragma unroll
                    for (int hf = 0; hf < 2; hf++) {
                        float* cc = acc[mt][np * 2 + hf];
                        MMAF16(cc, ah[mt], bh[np][hf * 2], bh[np][hf * 2 + 1]);
                        if (NP >= 2)
                            MMAF16(cc, al[mt], bh[np][hf * 2], bh[np][hf * 2 + 1]);
                        if (NP == 3)
                            MMAF16(cc, ah[mt], bl[np][hf * 2], bl[np][hf * 2 + 1]);
                    }
        }
        __syncthreads();
        if (kt + 2 < nk) load_stage(kt & 1, (kt + 2) << 5);
        else asm volatile("cp.async.commit_group;\n" ::: "memory");
    }

    // ---------------- epilogue ----------------
    float bj[8];
#pragma unroll
    for (int nt = 0; nt < 4; nt++) {
        int col = n0 + wn * 32 + nt * 8 + ((lane & 3) << 1);
        bj[nt * 2 + 0] = HASBIAS ? bias[col] : 0.f;
        bj[nt * 2 + 1] = HASBIAS ? bias[col + 1] : 0.f;
    }
#pragma unroll
    for (int mt = 0; mt < 4; mt++) {
#pragma unroll
        for (int hf = 0; hf < 2; hf++) {
            int row = m0 + wm * 64 + mt * 16 + (lane >> 2) + hf * 8;
            float vv[8];
            float vmax = -INFINITY;
#pragma unroll
            for (int nt = 0; nt < 4; nt++) {
#pragma unroll
                for (int j = 0; j < 2; j++) {
                    float v = acc[mt][nt][hf * 2 + j] + bj[nt * 2 + j];
                    if (RELU) v = fmaxf(v, 0.f);
                    vv[nt * 2 + j] = v;
                    vmax = fmaxf(vmax, v);
                }
            }
#pragma unroll
            for (int nt = 0; nt < 4; nt++) {
                int col = n0 + wn * 32 + nt * 8 + ((lane & 3) << 1);
                if (OUTMODE == 1) {
                    __half h0 = __float2half(vv[nt * 2]);
                    __half h1 = __float2half(vv[nt * 2 + 1]);
                    *(__half2*)(Ch + (size_t)row * N + col) = __halves2half2(h0, h1);
                    *(__half2*)(Cl + (size_t)row * N + col) = __halves2half2(
                        __float2half(vv[nt * 2] - __half2float(h0)),
                        __float2half(vv[nt * 2 + 1] - __half2float(h1)));
                } else if (OUTMODE == 2) {
                    *(__half2*)(Ch + (size_t)row * N + col) = __halves2half2(
                        __float2half(vv[nt * 2]), __float2half(vv[nt * 2 + 1]));
                } else {
                    float2 o; o.x = vv[nt * 2]; o.y = vv[nt * 2 + 1];
                    *(float2*)(C + (size_t)row * N + col) = o;
                }
            }
            if (LSE) {
                float rs = 0.f;
#pragma unroll
                for (int k = 0; k < 8; k++) rs += fast_exp(vv[k] - vmax);
                float rm = vmax;
#pragma unroll
                for (int off = 1; off <= 2; off <<= 1) {
                    float m2 = __shfl_xor_sync(0xFFFFFFFFu, rm, off);
                    float s2 = __shfl_xor_sync(0xFFFFFFFFu, rs, off);
                    float mn = fmaxf(rm, m2);
                    rs = rs * fast_exp(rm - mn) + s2 * fast_exp(m2 - mn);
                    rm = mn;
                }
                if ((lane & 3) == 0) {
                    int pcol = blockIdx.y * 4 + wn;
                    g_pm[(size_t)row * PN_ + pcol] = rm;
                    g_ps[(size_t)row * PN_ + pcol] = rs;
                }
            }
        }
    }
}

// ---------------- causal attention (fp32, online softmax) -------------------
// work-balanced: each block processes query tile (7-bx) then tile bx
// -> uniform 18 key-chunks per block; grid (T/256, B*H)
__global__ __launch_bounds__(128) void attn_kernel() {
    __shared__ float kv[64][64];
    __shared__ float sc[64][128];
    const int z   = blockIdx.y;
    const int b   = z >> 4;
    const int hh  = z & 15;
    const int tid = threadIdx.x;
    const int ntiles = T_ / 128;               // 8

#pragma unroll
    for (int half = 0; half < 2; half++) {
        const int bx = half == 0 ? (ntiles - 1 - blockIdx.x) : blockIdx.x;
        const int t  = bx * 128 + tid;

        const float4* qp = (const float4*)(g_qkv + (size_t)(b * T_ + t) * QKV3 + hh * HS_);
        float q[64];
#pragma unroll
        for (int d4 = 0; d4 < 16; d4++) {
            float4 qq = qp[d4];
            q[d4 * 4 + 0] = qq.x * 8.0f;       // * sqrt(HS)
            q[d4 * 4 + 1] = qq.y * 8.0f;
            q[d4 * 4 + 2] = qq.z * 8.0f;
            q[d4 * 4 + 3] = qq.w * 8.0f;
        }

        float acc[64];
#pragma unroll
        for (int d = 0; d < 64; d++) acc[d] = 0.f;
        float m = -INFINITY, l = 0.f;

        const int smax = bx * 128 + 127;
        for (int s0 = 0; s0 <= smax; s0 += 64) {
            const float* kbase = g_qkv + (size_t)(b * T_ + s0) * QKV3 + D_ + hh * HS_;
#pragma unroll
            for (int i = 0; i < 8; i++) {
                int lin = tid + 128 * i;
                int row = lin >> 4, c4 = lin & 15;
                *(float4*)&kv[row][c4 * 4] =
                    *(const float4*)(kbase + (size_t)row * QKV3 + c4 * 4);
            }
            __syncthreads();

            int cnt = t - s0 + 1;
            cnt = cnt < 0 ? 0 : (cnt > 64 ? 64 : cnt);
            for (int j = 0; j < cnt; j++) {
                const float4* kr = (const float4*)kv[j];
                float s = 0.f;
#pragma unroll
                for (int d4 = 0; d4 < 16; d4++) {
                    float4 kk = kr[d4];
                    s = fmaf(q[d4 * 4 + 0], kk.x, s);
                    s = fmaf(q[d4 * 4 + 1], kk.y, s);
                    s = fmaf(q[d4 * 4 + 2], kk.z, s);
                    s = fmaf(q[d4 * 4 + 3], kk.w, s);
                }
                sc[j][tid] = s;
            }
            __syncthreads();

            const float* vbase = g_qkv + (size_t)(b * T_ + s0) * QKV3 + 2 * D_ + hh * HS_;
#pragma unroll
            for (int i = 0; i < 8; i++) {
                int lin = tid + 128 * i;
                int row = lin >> 4, c4 = lin & 15;
                *(float4*)&kv[row][c4 * 4] =
                    *(const float4*)(vbase + (size_t)row * QKV3 + c4 * 4);
            }
            __syncthreads();

            if (cnt > 0) {
                float tmax = -INFINITY;
                for (int j = 0; j < cnt; j++) tmax = fmaxf(tmax, sc[j][tid]);
                float mn = fmaxf(m, tmax);
                float scale = __expf(m - mn);
                l *= scale;
#pragma unroll
                for (int d = 0; d < 64; d++) acc[d] *= scale;
                for (int j = 0; j < cnt; j++) {
                    float p = __expf(sc[j][tid] - mn);
                    l += p;
                    const float4* vr = (const float4*)kv[j];
#pragma unroll
                    for (int d4 = 0; d4 < 16; d4++) {
                        float4 vv4 = vr[d4];
                        acc[d4 * 4 + 0] = fmaf(p, vv4.x, acc[d4 * 4 + 0]);
                        acc[d4 * 4 + 1] = fmaf(p, vv4.y, acc[d4 * 4 + 1]);
                        acc[d4 * 4 + 2] = fmaf(p, vv4.z, acc[d4 * 4 + 2]);
                        acc[d4 * 4 + 3] = fmaf(p, vv4.w, acc[d4 * 4 + 3]);
                    }
                }
                m = mn;
            }
            __syncthreads();
        }

        float inv = 1.f / l;
        size_t obase = (size_t)(b * T_ + t) * D_ + hh * HS_;
#pragma unroll
        for (int d = 0; d < 64; d++) {
            float v = acc[d] * inv;
            __half hv = __float2half(v);
            g_oh[obase + d] = hv;
            g_ol[obase + d] = __float2half(v - __half2float(hv));
        }
        __syncthreads();
    }
}

// ---------------- loss from LSE partials -------------------------------------
__global__ __launch_bounds__(256) void loss_partial_kernel(const float* __restrict__ logits,
                                                           const int* __restrict__ y) {
    __shared__ float sm_m[256], sm_s[256];
    int row = blockIdx.x;
    int tid = threadIdx.x;
    float m = -INFINITY, s = 0.f;
    for (int i = tid; i < PN_; i += 256) {
        float m2 = g_pm[(size_t)row * PN_ + i];
        float s2 = g_ps[(size_t)row * PN_ + i];
        float mn = fmaxf(m, m2);
        s = s * fast_exp(m - mn) + s2 * fast_exp(m2 - mn);
        m = mn;
    }
    sm_m[tid] = m; sm_s[tid] = s;
    __syncthreads();
    for (int k = 128; k > 0; k >>= 1) {
        if (tid < k) {
            float m2 = sm_m[tid + k], s2 = sm_s[tid + k];
            float mn = fmaxf(sm_m[tid], m2);
            sm_s[tid] = sm_s[tid] * fast_exp(sm_m[tid] - mn) + s2 * fast_exp(m2 - mn);
            sm_m[tid] = mn;
        }
        __syncthreads();
    }
    if (tid == 0) {
        g_loss[row] = sm_m[0] + logf(sm_s[0]) - logits[(size_t)row * V_ + y[row]];
    }
}

__global__ __launch_bounds__(256) void loss_mean_kernel(float* out) {
    __shared__ float red[256];
    int tid = threadIdx.x;
    float s = 0.f;
    for (int i = tid; i < BT_; i += 256) s += g_loss[i];
    red[tid] = s;
    __syncthreads();
    for (int k = 128; k > 0; k >>= 1) {
        if (tid < k) red[tid] += red[tid + k];
        __syncthreads();
    }
    if (tid == 0) *out = red[0] / (float)BT_;
}

// ---------------- launch ----------------------------------------------------
extern "C" void kernel_launch(void* const* d_in, const int* in_sizes, int n_in,
                              void* d_out, int out_size) {
    const int*   x   = (const int*)d_in[0];
    const int*   y   = (const int*)d_in[1];
    const float* tok = (const float*)d_in[2];
    const float* pos = (const float*)d_in[3];
    const float* Wq  = (const float*)d_in[4];
    const float* Wk  = (const float*)d_in[5];
    const float* Wv  = (const float*)d_in[6];
    const float* ffw = (const float*)d_in[7];
    const float* ffb = (const float*)d_in[8];
    const float* fcw = (const float*)d_in[9];
    const float* fcb = (const float*)d_in[10];
    float* out = (float*)d_out;

    __half *phh, *phl, *poh, *pol, *pfh;
    __half *pwqh, *pwfh, *pwfl, *pwch;
    float *pqkv;
    cudaGetSymbolAddress((void**)&phh, g_hh);
    cudaGetSymbolAddress((void**)&phl, g_hl);
    cudaGetSymbolAddress((void**)&poh, g_oh);
    cudaGetSymbolAddress((void**)&pol, g_ol);
    cudaGetSymbolAddress((void**)&pfh, g_fh);
    cudaGetSymbolAddress((void**)&pwqh, g_wqkvh);
    cudaGetSymbolAddress((void**)&pwfh, g_wfh);
    cudaGetSymbolAddress((void**)&pwfl, g_wfl);
    cudaGetSymbolAddress((void**)&pwch, g_wch);
    cudaGetSymbolAddress((void**)&pqkv, g_qkv);

    const int smem3 = 2 * 4 * ATILE * 2;   // 81920 B (Ah,Al,Bh,Bl x2)
    const int smem2 = 2 * 3 * ATILE * 2;   // 61440 B (Ah,Al,Bh x2)
    const int smem1 = 2 * 2 * ATILE * 2;   // 40960 B (Ah,Bh x2)
    cudaFuncSetAttribute(mma_gemm<2,0,0,0,0>, cudaFuncAttributeMaxDynamicSharedMemorySize, smem2);
    cudaFuncSetAttribute(mma_gemm<3,1,1,2,0>, cudaFuncAttributeMaxDynamicSharedMemorySize, smem3);
    cudaFuncSetAttribute(mma_gemm<1,1,0,0,1>, cudaFuncAttributeMaxDynamicSharedMemorySize, smem1);

    // embedding (writes split h)
    embed_split<<<(BT_ * E_ / 4) / 256, 256>>>(x, tok, pos);

    // weight conversions (transpose + split)
    wsplit<1,0><<<dim3(D_/32, E_/32), 256>>>(Wq, pwqh,           nullptr, E_, D_);
    wsplit<1,0><<<dim3(D_/32, E_/32), 256>>>(Wk, pwqh + D_*E_,   nullptr, E_, D_);
    wsplit<1,0><<<dim3(D_/32, E_/32), 256>>>(Wv, pwqh + 2*D_*E_, nullptr, E_, D_);
    wsplit<0,1><<<dim3(D_/32, D_/32), 256>>>(ffw, pwfh, pwfl, D_, D_);
    wsplit<0,0><<<dim3(V_/32, D_/32), 256>>>(fcw, pwch, nullptr, D_, V_);

    // fused QKV GEMM: [4096,3072] = h @ [Wq|Wk|Wv]^T  (2-pass: exact-A x Bh)
    mma_gemm<2,0,0,0,0><<<dim3(BT_/128, QKV3/128), 256, smem2>>>(
        phh, phl, pwqh, nullptr, nullptr, pqkv, nullptr, nullptr, BT_, QKV3, E_);

    // attention (work-balanced tile pairs)
    attn_kernel<<<dim3(T_/256, B_*H_), 128>>>();

    // FF: relu(o @ ff_w + ff_b), hi-only output (3-pass)
    mma_gemm<3,1,1,2,0><<<dim3(BT_/128, D_/128), 256, smem3>>>(
        poh, pol, pwfh, pwfl, ffb, nullptr, pfh, nullptr, BT_, D_, D_);

    // logits: ff @ fc_w + fc_b -> d_out fp32 (1-pass, fused LSE partials)
    mma_gemm<1,1,0,0,1><<<dim3(BT_/128, V_/128), 256, smem1>>>(
        pfh, nullptr, pwch, nullptr, fcb, out, nullptr, nullptr, BT_, V_, D_);

    // loss
    loss_partial_kernel<<<BT_, 256>>>(out, y);
    long long logits_elems = (long long)BT_ * V_;
    if ((long long)out_size > logits_elems) {
        loss_mean_kernel<<<1, 256>>>(out + (size_t)logits_elems);
    }
}

// round 11
// speedup vs baseline: 1.1602x; 1.0632x over previous
#include <cuda_runtime.h>
#include <cuda_fp16.h>
#include <cstdint>
#include <math.h>

#define B_  4
#define T_  1024
#define E_  1024
#define H_  16
#define HS_ 64
#define D_  1024
#define V_  32000
#define BT_ 4096
#define QKV3 (3*D_)
#define PN_  (V_/32)        // LSE partials per row

// ---------------- scratch (device globals; no allocation allowed) ----------
__device__ __half g_hh[BT_*E_], g_hl[BT_*E_];          // embed split
__device__ float  g_qkv[BT_*QKV3];                      // q|k|v fp32
__device__ __half g_oh[BT_*D_], g_ol[BT_*D_];          // attn out split
__device__ __half g_fh[BT_*D_];                         // ff out hi only
__device__ __half g_wqkvh[(size_t)E_*QKV3];             // [k][n] hi
__device__ __half g_wfh[(size_t)D_*D_], g_wfl[(size_t)D_*D_];   // [k][n]
__device__ __half g_wch[(size_t)D_*V_];                 // [k][n] hi
__device__ float  g_pm[(size_t)BT_*PN_], g_ps[(size_t)BT_*PN_];
__device__ float  g_loss[BT_];

// ---------------- FFMA-only exp (used ONLY in low-register contexts) --------
__device__ __forceinline__ float fast_exp(float x) {
    float y = fmaxf(x * 1.44269504f, -126.0f);
    float r = y + 12582912.0f;
    int   n = __float_as_int(r) - 0x4B400000;
    float f = y - (r - 12582912.0f);
    float p =             1.33335581e-3f;
    p = fmaf(p, f, 9.61812911e-3f);
    p = fmaf(p, f, 5.55041087e-2f);
    p = fmaf(p, f, 2.40226507e-1f);
    p = fmaf(p, f, 6.93147181e-1f);
    p = fmaf(p, f, 1.0f);
    return p * __int_as_float((n + 127) << 23);
}

// ---------------- embedding: h = tok_emb[x] + pos_emb[t], split to fp16 -----
__global__ __launch_bounds__(256) void embed_split(const int* __restrict__ x,
                                                   const float* __restrict__ tok,
                                                   const float* __restrict__ pos) {
    int idx = blockIdx.x * 256 + threadIdx.x;
    int r = idx >> 8;
    int c = idx & 255;
    int token = x[r];
    int t = r & (T_ - 1);
    float4 a = ((const float4*)tok)[(size_t)token * 256 + c];
    float4 b = ((const float4*)pos)[(size_t)t * 256 + c];
    float v[4] = {a.x + b.x, a.y + b.y, a.z + b.z, a.w + b.w};
    __half h[4], l[4];
#pragma unroll
    for (int i = 0; i < 4; i++) {
        h[i] = __float2half(v[i]);
        l[i] = __float2half(v[i] - __half2float(h[i]));
    }
    ((__half2*)g_hh)[idx * 2 + 0] = __halves2half2(h[0], h[1]);
    ((__half2*)g_hh)[idx * 2 + 1] = __halves2half2(h[2], h[3]);
    ((__half2*)g_hl)[idx * 2 + 0] = __halves2half2(l[0], l[1]);
    ((__half2*)g_hl)[idx * 2 + 1] = __halves2half2(l[2], l[3]);
}

// ---------------- elementwise fp32 -> fp16 convert (no transpose!) ----------
template <int WLO>
__global__ __launch_bounds__(256) void wconv(const float* __restrict__ W,
                                             __half* __restrict__ hi,
                                             __half* __restrict__ lo) {
    size_t i = ((size_t)blockIdx.x * 256 + threadIdx.x) * 4;
    float4 v = *(const float4*)(W + i);
    __half h0 = __float2half(v.x), h1 = __float2half(v.y);
    __half h2 = __float2half(v.z), h3 = __float2half(v.w);
    ((__half2*)(hi + i))[0] = __halves2half2(h0, h1);
    ((__half2*)(hi + i))[1] = __halves2half2(h2, h3);
    if (WLO) {
        ((__half2*)(lo + i))[0] = __halves2half2(
            __float2half(v.x - __half2float(h0)),
            __float2half(v.y - __half2float(h1)));
        ((__half2*)(lo + i))[1] = __halves2half2(
            __float2half(v.z - __half2float(h2)),
            __float2half(v.w - __half2float(h3)));
    }
}

// QKV gather convert: W[H][E][HS] fp32 -> out[k][h*64+hs] fp16 (stride QKV3)
__global__ __launch_bounds__(256) void wconv_qkv(const float* __restrict__ W,
                                                 __half* __restrict__ out) {
    int idx = blockIdx.x * 256 + threadIdx.x;  // over H*E*HS/4
    int i = idx << 2;
    int h  = i >> 16;            // / (E*HS)
    int k  = (i >> 6) & 1023;
    int hs = i & 63;
    float4 v = ((const float4*)W)[idx];
    size_t o = (size_t)k * QKV3 + h * 64 + hs;
    ((__half2*)(out + o))[0] = __halves2half2(__float2half(v.x), __float2half(v.y));
    ((__half2*)(out + o))[1] = __halves2half2(__float2half(v.z), __float2half(v.w));
}

// ---------------- split-fp16 tensor-core GEMM (B in [K][N] layout) ----------
// NP=3: ah*bh + ah*bl + al*bh ; NP=2: ah*bh + al*bh ; NP=1: ah*bh
// OUTMODE: 0 = fp32 C, 1 = half hi+lo, 2 = half hi only
#define SSTR  40
#define ATILE (128*SSTR)
#define SSTRB 136
#define BTILE (32*SSTRB)

__device__ __forceinline__ void cpa16(uint32_t dst, const void* src) {
    asm volatile("cp.async.cg.shared.global [%0], [%1], 16;\n" :: "r"(dst), "l"(src));
}
#define LDM4(R, ADDR) \
    asm volatile("ldmatrix.sync.aligned.m8n8.x4.shared.b16 {%0,%1,%2,%3}, [%4];" \
        : "=r"(R[0]), "=r"(R[1]), "=r"(R[2]), "=r"(R[3]) : "r"(ADDR))
#define LDM4T(R, ADDR) \
    asm volatile("ldmatrix.sync.aligned.m8n8.x4.trans.shared.b16 {%0,%1,%2,%3}, [%4];" \
        : "=r"(R[0]), "=r"(R[1]), "=r"(R[2]), "=r"(R[3]) : "r"(ADDR))
#define MMAF16(Cc, Aa, B0, B1) \
    asm volatile("mma.sync.aligned.m16n8k16.row.col.f32.f16.f16.f32 " \
        "{%0,%1,%2,%3}, {%4,%5,%6,%7}, {%8,%9}, {%0,%1,%2,%3};" \
        : "+f"(Cc[0]), "+f"(Cc[1]), "+f"(Cc[2]), "+f"(Cc[3]) \
        : "r"(Aa[0]), "r"(Aa[1]), "r"(Aa[2]), "r"(Aa[3]), "r"(B0), "r"(B1))

template <int NP, int HASBIAS, int RELU, int OUTMODE, int LSE>
__global__ __launch_bounds__(256) void mma_gemm(
    const __half* __restrict__ Ah, const __half* __restrict__ Al,
    const __half* __restrict__ Bh, const __half* __restrict__ Bl,
    const float* __restrict__ bias, float* __restrict__ C,
    __half* __restrict__ Ch, __half* __restrict__ Cl,
    int M, int N, int K)
{
    extern __shared__ __half sm[];
    constexpr int NA  = (NP >= 2) ? 2 : 1;
    constexpr int NB  = (NP == 3) ? 2 : 1;
    constexpr int STG = NA * ATILE + NB * BTILE;
    const int m0 = blockIdx.x * 128, n0 = blockIdx.y * 128;
    const int tid = threadIdx.x;
    const int lane = tid & 31, w = tid >> 5;
    const int wm = w >> 2, wn = w & 3;
    const uint32_t smb = (uint32_t)__cvta_generic_to_shared(sm);

    const int nk = K >> 5;

    auto load_stage = [&](int s, int k0g) {
#pragma unroll
        for (int a = 0; a < NA; a++) {
#pragma unroll
            for (int hlf = 0; hlf < 2; hlf++) {
                int rem = (hlf << 8) + tid;
                int row = rem >> 2, seg = tid & 3;
                const __half* gp = (a == 0) ? Ah : Al;
                const __half* src = gp + (size_t)(m0 + row) * K + k0g + seg * 8;
                uint32_t dst = smb + (uint32_t)((s * STG + a * ATILE + row * SSTR + seg * 8) << 1);
                cpa16(dst, src);
            }
        }
#pragma unroll
        for (int ba = 0; ba < NB; ba++) {
#pragma unroll
            for (int it = 0; it < 2; it++) {
                int idx = it * 256 + tid;
                int row = idx >> 4, seg = idx & 15;   // row: k 0..31, seg: n chunk
                const __half* gp = (ba == 0) ? Bh : Bl;
                const __half* src = gp + (size_t)(k0g + row) * N + n0 + seg * 8;
                uint32_t dst = smb + (uint32_t)((s * STG + NA * ATILE + ba * BTILE
                                                 + row * SSTRB + seg * 8) << 1);
                cpa16(dst, src);
            }
        }
        asm volatile("cp.async.commit_group;\n" ::: "memory");
    };

    load_stage(0, 0);
    load_stage(1, 32);

    float acc[4][4][4];
#pragma unroll
    for (int a = 0; a < 4; a++)
#pragma unroll
        for (int b = 0; b < 4; b++)
#pragma unroll
            for (int c = 0; c < 4; c++) acc[a][b][c] = 0.f;

    const int t8 = lane >> 3, r8 = lane & 7;
    const int g2 = lane >> 3;                 // ldmatrix address group 0..3

    for (int kt = 0; kt < nk; kt++) {
        asm volatile("cp.async.wait_group 1;\n" ::: "memory");
        __syncthreads();
        const uint32_t base = smb + (uint32_t)(((kt & 1) * STG) << 1);
#pragma unroll
        for (int kk = 0; kk < 2; kk++) {
            const int kof = kk << 4;
            uint32_t ah[4][4], al[4][4], bh[2][4], bl[2][4];
#pragma unroll
            for (int mt = 0; mt < 4; mt++) {
                int mrow = wm * 64 + mt * 16 + ((t8 & 1) << 3) + r8;
                int kcol = kof + ((t8 >> 1) << 3);
                uint32_t ad = base + (uint32_t)((mrow * SSTR + kcol) << 1);
                LDM4(ah[mt], ad);
                if (NP >= 2) LDM4(al[mt], ad + (ATILE << 1));
            }
#pragma unroll
            for (int np = 0; np < 2; np++) {
                // B tile [k][n] with ldmatrix.trans:
                // groups: g&1 -> k half (0/8), g>>1 -> n half (0/8)
                int krow = kof + ((g2 & 1) << 3) + (lane & 7);
                int ncol = wn * 32 + np * 16 + ((g2 >> 1) << 3);
                uint32_t bd = base + (uint32_t)((NA * ATILE + krow * SSTRB + ncol) << 1);
                LDM4T(bh[np], bd);
                if (NP == 3) LDM4T(bl[np], bd + (BTILE << 1));
            }
#pragma unroll
            for (int mt = 0; mt < 4; mt++)
#pragma unroll
                for (int np = 0; np < 2; np++)
#pragma unroll
                    for (int hf = 0; hf < 2; hf++) {
                        float* cc = acc[mt][np * 2 + hf];
                        MMAF16(cc, ah[mt], bh[np][hf * 2], bh[np][hf * 2 + 1]);
                        if (NP >= 2)
                            MMAF16(cc, al[mt], bh[np][hf * 2], bh[np][hf * 2 + 1]);
                        if (NP == 3)
                            MMAF16(cc, ah[mt], bl[np][hf * 2], bl[np][hf * 2 + 1]);
                    }
        }
        __syncthreads();
        if (kt + 2 < nk) load_stage(kt & 1, (kt + 2) << 5);
        else asm volatile("cp.async.commit_group;\n" ::: "memory");
    }

    // ---------------- epilogue ----------------
    float bj[8];
#pragma unroll
    for (int nt = 0; nt < 4; nt++) {
        int col = n0 + wn * 32 + nt * 8 + ((lane & 3) << 1);
        bj[nt * 2 + 0] = HASBIAS ? bias[col] : 0.f;
        bj[nt * 2 + 1] = HASBIAS ? bias[col + 1] : 0.f;
    }
#pragma unroll
    for (int mt = 0; mt < 4; mt++) {
#pragma unroll
        for (int hf = 0; hf < 2; hf++) {
            int row = m0 + wm * 64 + mt * 16 + (lane >> 2) + hf * 8;
            float vv[8];
            float vmax = -INFINITY;
#pragma unroll
            for (int nt = 0; nt < 4; nt++) {
#pragma unroll
                for (int j = 0; j < 2; j++) {
                    float v = acc[mt][nt][hf * 2 + j] + bj[nt * 2 + j];
                    if (RELU) v = fmaxf(v, 0.f);
                    vv[nt * 2 + j] = v;
                    vmax = fmaxf(vmax, v);
                }
            }
#pragma unroll
            for (int nt = 0; nt < 4; nt++) {
                int col = n0 + wn * 32 + nt * 8 + ((lane & 3) << 1);
                if (OUTMODE == 1) {
                    __half h0 = __float2half(vv[nt * 2]);
                    __half h1 = __float2half(vv[nt * 2 + 1]);
                    *(__half2*)(Ch + (size_t)row * N + col) = __halves2half2(h0, h1);
                    *(__half2*)(Cl + (size_t)row * N + col) = __halves2half2(
                        __float2half(vv[nt * 2] - __half2float(h0)),
                        __float2half(vv[nt * 2 + 1] - __half2float(h1)));
                } else if (OUTMODE == 2) {
                    *(__half2*)(Ch + (size_t)row * N + col) = __halves2half2(
                        __float2half(vv[nt * 2]), __float2half(vv[nt * 2 + 1]));
                } else {
                    float2 o; o.x = vv[nt * 2]; o.y = vv[nt * 2 + 1];
                    *(float2*)(C + (size_t)row * N + col) = o;
                }
            }
            if (LSE) {
                float rs = 0.f;
#pragma unroll
                for (int k = 0; k < 8; k++) rs += fast_exp(vv[k] - vmax);
                float rm = vmax;
#pragma unroll
                for (int off = 1; off <= 2; off <<= 1) {
                    float m2 = __shfl_xor_sync(0xFFFFFFFFu, rm, off);
                    float s2 = __shfl_xor_sync(0xFFFFFFFFu, rs, off);
                    float mn = fmaxf(rm, m2);
                    rs = rs * fast_exp(rm - mn) + s2 * fast_exp(m2 - mn);
                    rm = mn;
                }
                if ((lane & 3) == 0) {
                    int pcol = blockIdx.y * 4 + wn;
                    g_pm[(size_t)row * PN_ + pcol] = rm;
                    g_ps[(size_t)row * PN_ + pcol] = rs;
                }
            }
        }
    }
}

// ---------------- causal attention (fp32, online softmax, work-balanced) ----
__global__ __launch_bounds__(128) void attn_kernel() {
    __shared__ float kv[64][64];
    __shared__ float sc[64][128];
    const int z   = blockIdx.y;
    const int b   = z >> 4;
    const int hh  = z & 15;
    const int tid = threadIdx.x;
    const int ntiles = T_ / 128;               // 8

#pragma unroll
    for (int half = 0; half < 2; half++) {
        const int bx = half == 0 ? (ntiles - 1 - blockIdx.x) : blockIdx.x;
        const int t  = bx * 128 + tid;

        const float4* qp = (const float4*)(g_qkv + (size_t)(b * T_ + t) * QKV3 + hh * HS_);
        float q[64];
#pragma unroll
        for (int d4 = 0; d4 < 16; d4++) {
            float4 qq = qp[d4];
            q[d4 * 4 + 0] = qq.x * 8.0f;
            q[d4 * 4 + 1] = qq.y * 8.0f;
            q[d4 * 4 + 2] = qq.z * 8.0f;
            q[d4 * 4 + 3] = qq.w * 8.0f;
        }

        float acc[64];
#pragma unroll
        for (int d = 0; d < 64; d++) acc[d] = 0.f;
        float m = -INFINITY, l = 0.f;

        const int smax = bx * 128 + 127;
        for (int s0 = 0; s0 <= smax; s0 += 64) {
            const float* kbase = g_qkv + (size_t)(b * T_ + s0) * QKV3 + D_ + hh * HS_;
#pragma unroll
            for (int i = 0; i < 8; i++) {
                int lin = tid + 128 * i;
                int row = lin >> 4, c4 = lin & 15;
                *(float4*)&kv[row][c4 * 4] =
                    *(const float4*)(kbase + (size_t)row * QKV3 + c4 * 4);
            }
            __syncthreads();

            int cnt = t - s0 + 1;
            cnt = cnt < 0 ? 0 : (cnt > 64 ? 64 : cnt);
            for (int j = 0; j < cnt; j++) {
                const float4* kr = (const float4*)kv[j];
                float s = 0.f;
#pragma unroll
                for (int d4 = 0; d4 < 16; d4++) {
                    float4 kk = kr[d4];
                    s = fmaf(q[d4 * 4 + 0], kk.x, s);
                    s = fmaf(q[d4 * 4 + 1], kk.y, s);
                    s = fmaf(q[d4 * 4 + 2], kk.z, s);
                    s = fmaf(q[d4 * 4 + 3], kk.w, s);
                }
                sc[j][tid] = s;
            }
            __syncthreads();

            const float* vbase = g_qkv + (size_t)(b * T_ + s0) * QKV3 + 2 * D_ + hh * HS_;
#pragma unroll
            for (int i = 0; i < 8; i++) {
                int lin = tid + 128 * i;
                int row = lin >> 4, c4 = lin & 15;
                *(float4*)&kv[row][c4 * 4] =
                    *(const float4*)(vbase + (size_t)row * QKV3 + c4 * 4);
            }
            __syncthreads();

            if (cnt > 0) {
                float tmax = -INFINITY;
                for (int j = 0; j < cnt; j++) tmax = fmaxf(tmax, sc[j][tid]);
                float mn = fmaxf(m, tmax);
                float scale = __expf(m - mn);
                l *= scale;
#pragma unroll
                for (int d = 0; d < 64; d++) acc[d] *= scale;
                for (int j = 0; j < cnt; j++) {
                    float p = __expf(sc[j][tid] - mn);
                    l += p;
                    const float4* vr = (const float4*)kv[j];
#pragma unroll
                    for (int d4 = 0; d4 < 16; d4++) {
                        float4 vv4 = vr[d4];
                        acc[d4 * 4 + 0] = fmaf(p, vv4.x, acc[d4 * 4 + 0]);
                        acc[d4 * 4 + 1] = fmaf(p, vv4.y, acc[d4 * 4 + 1]);
                        acc[d4 * 4 + 2] = fmaf(p, vv4.z, acc[d4 * 4 + 2]);
                        acc[d4 * 4 + 3] = fmaf(p, vv4.w, acc[d4 * 4 + 3]);
                    }
                }
                m = mn;
            }
            __syncthreads();
        }

        float inv = 1.f / l;
        size_t obase = (size_t)(b * T_ + t) * D_ + hh * HS_;
#pragma unroll
        for (int d = 0; d < 64; d++) {
            float v = acc[d] * inv;
            __half hv = __float2half(v);
            g_oh[obase + d] = hv;
            g_ol[obase + d] = __float2half(v - __half2float(hv));
        }
        __syncthreads();
    }
}

// ---------------- loss from LSE partials -------------------------------------
__global__ __launch_bounds__(256) void loss_partial_kernel(const float* __restrict__ logits,
                                                           const int* __restrict__ y) {
    __shared__ float sm_m[256], sm_s[256];
    int row = blockIdx.x;
    int tid = threadIdx.x;
    float m = -INFINITY, s = 0.f;
    for (int i = tid; i < PN_; i += 256) {
        float m2 = g_pm[(size_t)row * PN_ + i];
        float s2 = g_ps[(size_t)row * PN_ + i];
        float mn = fmaxf(m, m2);
        s = s * fast_exp(m - mn) + s2 * fast_exp(m2 - mn);
        m = mn;
    }
    sm_m[tid] = m; sm_s[tid] = s;
    __syncthreads();
    for (int k = 128; k > 0; k >>= 1) {
        if (tid < k) {
            float m2 = sm_m[tid + k], s2 = sm_s[tid + k];
            float mn = fmaxf(sm_m[tid], m2);
            sm_s[tid] = sm_s[tid] * fast_exp(sm_m[tid] - mn) + s2 * fast_exp(m2 - mn);
            sm_m[tid] = mn;
        }
        __syncthreads();
    }
    if (tid == 0) {
        g_loss[row] = sm_m[0] + logf(sm_s[0]) - logits[(size_t)row * V_ + y[row]];
    }
}

__global__ __launch_bounds__(256) void loss_mean_kernel(float* out) {
    __shared__ float red[256];
    int tid = threadIdx.x;
    float s = 0.f;
    for (int i = tid; i < BT_; i += 256) s += g_loss[i];
    red[tid] = s;
    __syncthreads();
    for (int k = 128; k > 0; k >>= 1) {
        if (tid < k) red[tid] += red[tid + k];
        __syncthreads();
    }
    if (tid == 0) *out = red[0] / (float)BT_;
}

// ---------------- launch ----------------------------------------------------
extern "C" void kernel_launch(void* const* d_in, const int* in_sizes, int n_in,
                              void* d_out, int out_size) {
    const int*   x   = (const int*)d_in[0];
    const int*   y   = (const int*)d_in[1];
    const float* tok = (const float*)d_in[2];
    const float* pos = (const float*)d_in[3];
    const float* Wq  = (const float*)d_in[4];
    const float* Wk  = (const float*)d_in[5];
    const float* Wv  = (const float*)d_in[6];
    const float* ffw = (const float*)d_in[7];
    const float* ffb = (const float*)d_in[8];
    const float* fcw = (const float*)d_in[9];
    const float* fcb = (const float*)d_in[10];
    float* out = (float*)d_out;

    __half *phh, *phl, *poh, *pol, *pfh;
    __half *pwqh, *pwfh, *pwfl, *pwch;
    float *pqkv;
    cudaGetSymbolAddress((void**)&phh, g_hh);
    cudaGetSymbolAddress((void**)&phl, g_hl);
    cudaGetSymbolAddress((void**)&poh, g_oh);
    cudaGetSymbolAddress((void**)&pol, g_ol);
    cudaGetSymbolAddress((void**)&pfh, g_fh);
    cudaGetSymbolAddress((void**)&pwqh, g_wqkvh);
    cudaGetSymbolAddress((void**)&pwfh, g_wfh);
    cudaGetSymbolAddress((void**)&pwfl, g_wfl);
    cudaGetSymbolAddress((void**)&pwch, g_wch);
    cudaGetSymbolAddress((void**)&pqkv, g_qkv);

    const int smem3 = 2 * (2 * ATILE + 2 * BTILE) * 2;   // NP=3
    const int smem2 = 2 * (2 * ATILE + 1 * BTILE) * 2;   // NP=2
    const int smem1 = 2 * (1 * ATILE + 1 * BTILE) * 2;   // NP=1
    cudaFuncSetAttribute(mma_gemm<2,0,0,0,0>, cudaFuncAttributeMaxDynamicSharedMemorySize, smem2);
    cudaFuncSetAttribute(mma_gemm<3,1,1,2,0>, cudaFuncAttributeMaxDynamicSharedMemorySize, smem3);
    cudaFuncSetAttribute(mma_gemm<1,1,0,0,1>, cudaFuncAttributeMaxDynamicSharedMemorySize, smem1);

    // embedding (writes split h)
    embed_split<<<(BT_ * E_ / 4) / 256, 256>>>(x, tok, pos);

    // weight converts (elementwise, no transpose)
    wconv_qkv<<<(H_*E_*HS_/4)/256, 256>>>(Wq, pwqh);
    wconv_qkv<<<(H_*E_*HS_/4)/256, 256>>>(Wk, pwqh + D_);
    wconv_qkv<<<(H_*E_*HS_/4)/256, 256>>>(Wv, pwqh + 2*D_);
    wconv<1><<<(D_*D_/4)/256, 256>>>(ffw, pwfh, pwfl);
    wconv<0><<<((size_t)D_*V_/4)/256, 256>>>(fcw, pwch, nullptr);

    // fused QKV GEMM: [4096,3072] = h @ Wqkv[k][n]  (2-pass: exact-A x Bh)
    mma_gemm<2,0,0,0,0><<<dim3(BT_/128, QKV3/128), 256, smem2>>>(
        phh, phl, pwqh, nullptr, nullptr, pqkv, nullptr, nullptr, BT_, QKV3, E_);

    // attention (work-balanced tile pairs)
    attn_kernel<<<dim3(T_/256, B_*H_), 128>>>();

    // FF: relu(o @ ff_w + ff_b), hi-only output (3-pass)
    mma_gemm<3,1,1,2,0><<<dim3(BT_/128, D_/128), 256, smem3>>>(
        poh, pol, pwfh, pwfl, ffb, nullptr, pfh, nullptr, BT_, D_, D_);

    // logits: ff @ fc_w + fc_b -> d_out fp32 (1-pass, fused LSE partials)
    mma_gemm<1,1,0,0,1><<<dim3(BT_/128, V_/128), 256, smem1>>>(
        pfh, nullptr, pwch, nullptr, fcb, out, nullptr, nullptr, BT_, V_, D_);

    // loss
    loss_partial_kernel<<<BT_, 256>>>(out, y);
    long long logits_elems = (long long)BT_ * V_;
    if ((long long)out_size > logits_elems) {
        loss_mean_kernel<<<1, 256>>>(out + (size_t)logits_elems);
    }
}

// round 12
// speedup vs baseline: 1.2972x; 1.1181x over previous
#include <cuda_runtime.h>
#include <cuda_fp16.h>
#include <cstdint>
#include <math.h>

#define B_  4
#define T_  1024
#define E_  1024
#define H_  16
#define HS_ 64
#define D_  1024
#define V_  32000
#define BT_ 4096
#define QKV3 (3*D_)
#define PN_  (V_/32)        // LSE partials per row

// ---------------- scratch (device globals; no allocation allowed) ----------
__device__ __half g_hh[BT_*E_];                         // embed fp16
__device__ float  g_qkv[BT_*QKV3];                      // q|k|v fp32
__device__ __half g_oh[BT_*D_];                         // attn out fp16
__device__ __half g_fh[BT_*D_];                         // ff out fp16
__device__ __half g_wqkvh[(size_t)E_*QKV3];             // [k][n]
__device__ __half g_wfh[(size_t)D_*D_];                 // [k][n]
__device__ __half g_wch[(size_t)D_*V_];                 // [k][n]
__device__ float  g_pm[(size_t)BT_*PN_], g_ps[(size_t)BT_*PN_];
__device__ float  g_loss[BT_];

// ---------------- FFMA-only exp (used ONLY in low-register contexts) --------
__device__ __forceinline__ float fast_exp(float x) {
    float y = fmaxf(x * 1.44269504f, -126.0f);
    float r = y + 12582912.0f;
    int   n = __float_as_int(r) - 0x4B400000;
    float f = y - (r - 12582912.0f);
    float p =             1.33335581e-3f;
    p = fmaf(p, f, 9.61812911e-3f);
    p = fmaf(p, f, 5.55041087e-2f);
    p = fmaf(p, f, 2.40226507e-1f);
    p = fmaf(p, f, 6.93147181e-1f);
    p = fmaf(p, f, 1.0f);
    return p * __int_as_float((n + 127) << 23);
}

// ---------------- embedding: h = tok_emb[x] + pos_emb[t] -> fp16 ------------
__global__ __launch_bounds__(256) void embed_split(const int* __restrict__ x,
                                                   const float* __restrict__ tok,
                                                   const float* __restrict__ pos) {
    int idx = blockIdx.x * 256 + threadIdx.x;
    int r = idx >> 8;
    int c = idx & 255;
    int token = x[r];
    int t = r & (T_ - 1);
    float4 a = ((const float4*)tok)[(size_t)token * 256 + c];
    float4 b = ((const float4*)pos)[(size_t)t * 256 + c];
    ((__half2*)g_hh)[idx * 2 + 0] = __halves2half2(
        __float2half(a.x + b.x), __float2half(a.y + b.y));
    ((__half2*)g_hh)[idx * 2 + 1] = __halves2half2(
        __float2half(a.z + b.z), __float2half(a.w + b.w));
}

// ---------------- elementwise fp32 -> fp16 convert ---------------------------
__global__ __launch_bounds__(256) void wconv(const float* __restrict__ W,
                                             __half* __restrict__ hi) {
    size_t i = ((size_t)blockIdx.x * 256 + threadIdx.x) * 4;
    float4 v = *(const float4*)(W + i);
    ((__half2*)(hi + i))[0] = __halves2half2(__float2half(v.x), __float2half(v.y));
    ((__half2*)(hi + i))[1] = __halves2half2(__float2half(v.z), __float2half(v.w));
}

// QKV gather convert: W[H][E][HS] fp32 -> out[k][h*64+hs] fp16 (stride QKV3)
__global__ __launch_bounds__(256) void wconv_qkv(const float* __restrict__ W,
                                                 __half* __restrict__ out) {
    int idx = blockIdx.x * 256 + threadIdx.x;
    int i = idx << 2;
    int h  = i >> 16;
    int k  = (i >> 6) & 1023;
    int hs = i & 63;
    float4 v = ((const float4*)W)[idx];
    size_t o = (size_t)k * QKV3 + h * 64 + hs;
    ((__half2*)(out + o))[0] = __halves2half2(__float2half(v.x), __float2half(v.y));
    ((__half2*)(out + o))[1] = __halves2half2(__float2half(v.z), __float2half(v.w));
}

// ---------------- fp16 tensor-core GEMM (B in [K][N] layout) ----------------
// OUTMODE: 0 = fp32 C, 2 = half C
#define SSTR  40
#define ATILE (128*SSTR)
#define SSTRB 136
#define BTILE (32*SSTRB)

__device__ __forceinline__ void cpa16(uint32_t dst, const void* src) {
    asm volatile("cp.async.cg.shared.global [%0], [%1], 16;\n" :: "r"(dst), "l"(src));
}
#define LDM4(R, ADDR) \
    asm volatile("ldmatrix.sync.aligned.m8n8.x4.shared.b16 {%0,%1,%2,%3}, [%4];" \
        : "=r"(R[0]), "=r"(R[1]), "=r"(R[2]), "=r"(R[3]) : "r"(ADDR))
#define LDM4T(R, ADDR) \
    asm volatile("ldmatrix.sync.aligned.m8n8.x4.trans.shared.b16 {%0,%1,%2,%3}, [%4];" \
        : "=r"(R[0]), "=r"(R[1]), "=r"(R[2]), "=r"(R[3]) : "r"(ADDR))
#define MMAF16(Cc, Aa, B0, B1) \
    asm volatile("mma.sync.aligned.m16n8k16.row.col.f32.f16.f16.f32 " \
        "{%0,%1,%2,%3}, {%4,%5,%6,%7}, {%8,%9}, {%0,%1,%2,%3};" \
        : "+f"(Cc[0]), "+f"(Cc[1]), "+f"(Cc[2]), "+f"(Cc[3]) \
        : "r"(Aa[0]), "r"(Aa[1]), "r"(Aa[2]), "r"(Aa[3]), "r"(B0), "r"(B1))

template <int HASBIAS, int RELU, int OUTMODE, int LSE>
__global__ __launch_bounds__(256) void mma_gemm(
    const __half* __restrict__ Ah,
    const __half* __restrict__ Bh,
    const float* __restrict__ bias, float* __restrict__ C,
    __half* __restrict__ Ch,
    int M, int N, int K)
{
    extern __shared__ __half sm[];
    constexpr int STG = ATILE + BTILE;
    const int m0 = blockIdx.x * 128, n0 = blockIdx.y * 128;
    const int tid = threadIdx.x;
    const int lane = tid & 31, w = tid >> 5;
    const int wm = w >> 2, wn = w & 3;
    const uint32_t smb = (uint32_t)__cvta_generic_to_shared(sm);

    const int nk = K >> 5;

    auto load_stage = [&](int s, int k0g) {
#pragma unroll
        for (int hlf = 0; hlf < 2; hlf++) {
            int rem = (hlf << 8) + tid;
            int row = rem >> 2, seg = tid & 3;
            const __half* src = Ah + (size_t)(m0 + row) * K + k0g + seg * 8;
            uint32_t dst = smb + (uint32_t)((s * STG + row * SSTR + seg * 8) << 1);
            cpa16(dst, src);
        }
#pragma unroll
        for (int it = 0; it < 2; it++) {
            int idx = it * 256 + tid;
            int row = idx >> 4, seg = idx & 15;
            const __half* src = Bh + (size_t)(k0g + row) * N + n0 + seg * 8;
            uint32_t dst = smb + (uint32_t)((s * STG + ATILE + row * SSTRB + seg * 8) << 1);
            cpa16(dst, src);
        }
        asm volatile("cp.async.commit_group;\n" ::: "memory");
    };

    load_stage(0, 0);
    load_stage(1, 32);

    float acc[4][4][4];
#pragma unroll
    for (int a = 0; a < 4; a++)
#pragma unroll
        for (int b = 0; b < 4; b++)
#pragma unroll
            for (int c = 0; c < 4; c++) acc[a][b][c] = 0.f;

    const int t8 = lane >> 3, r8 = lane & 7;
    const int g2 = lane >> 3;

    for (int kt = 0; kt < nk; kt++) {
        asm volatile("cp.async.wait_group 1;\n" ::: "memory");
        __syncthreads();
        const uint32_t base = smb + (uint32_t)(((kt & 1) * STG) << 1);
#pragma unroll
        for (int kk = 0; kk < 2; kk++) {
            const int kof = kk << 4;
            uint32_t ah[4][4], bh[2][4];
#pragma unroll
            for (int mt = 0; mt < 4; mt++) {
                int mrow = wm * 64 + mt * 16 + ((t8 & 1) << 3) + r8;
                int kcol = kof + ((t8 >> 1) << 3);
                uint32_t ad = base + (uint32_t)((mrow * SSTR + kcol) << 1);
                LDM4(ah[mt], ad);
            }
#pragma unroll
            for (int np = 0; np < 2; np++) {
                int krow = kof + ((g2 & 1) << 3) + (lane & 7);
                int ncol = wn * 32 + np * 16 + ((g2 >> 1) << 3);
                uint32_t bd = base + (uint32_t)((ATILE + krow * SSTRB + ncol) << 1);
                LDM4T(bh[np], bd);
            }
#pragma unroll
            for (int mt = 0; mt < 4; mt++)
#pragma unroll
                for (int np = 0; np < 2; np++)
#pragma unroll
                    for (int hf = 0; hf < 2; hf++) {
                        float* cc = acc[mt][np * 2 + hf];
                        MMAF16(cc, ah[mt], bh[np][hf * 2], bh[np][hf * 2 + 1]);
                    }
        }
        __syncthreads();
        if (kt + 2 < nk) load_stage(kt & 1, (kt + 2) << 5);
        else asm volatile("cp.async.commit_group;\n" ::: "memory");
    }

    // ---------------- epilogue ----------------
    float bj[8];
#pragma unroll
    for (int nt = 0; nt < 4; nt++) {
        int col = n0 + wn * 32 + nt * 8 + ((lane & 3) << 1);
        bj[nt * 2 + 0] = HASBIAS ? bias[col] : 0.f;
        bj[nt * 2 + 1] = HASBIAS ? bias[col + 1] : 0.f;
    }
#pragma unroll
    for (int mt = 0; mt < 4; mt++) {
#pragma unroll
        for (int hf = 0; hf < 2; hf++) {
            int row = m0 + wm * 64 + mt * 16 + (lane >> 2) + hf * 8;
            float vv[8];
            float vmax = -INFINITY;
#pragma unroll
            for (int nt = 0; nt < 4; nt++) {
#pragma unroll
                for (int j = 0; j < 2; j++) {
                    float v = acc[mt][nt][hf * 2 + j] + bj[nt * 2 + j];
                    if (RELU) v = fmaxf(v, 0.f);
                    vv[nt * 2 + j] = v;
                    vmax = fmaxf(vmax, v);
                }
            }
#pragma unroll
            for (int nt = 0; nt < 4; nt++) {
                int col = n0 + wn * 32 + nt * 8 + ((lane & 3) << 1);
                if (OUTMODE == 2) {
                    *(__half2*)(Ch + (size_t)row * N + col) = __halves2half2(
                        __float2half(vv[nt * 2]), __float2half(vv[nt * 2 + 1]));
                } else {
                    float2 o; o.x = vv[nt * 2]; o.y = vv[nt * 2 + 1];
                    *(float2*)(C + (size_t)row * N + col) = o;
                }
            }
            if (LSE) {
                float rs = 0.f;
#pragma unroll
                for (int k = 0; k < 8; k++) rs += fast_exp(vv[k] - vmax);
                float rm = vmax;
#pragma unroll
                for (int off = 1; off <= 2; off <<= 1) {
                    float m2 = __shfl_xor_sync(0xFFFFFFFFu, rm, off);
                    float s2 = __shfl_xor_sync(0xFFFFFFFFu, rs, off);
                    float mn = fmaxf(rm, m2);
                    rs = rs * fast_exp(rm - mn) + s2 * fast_exp(m2 - mn);
                    rm = mn;
                }
                if ((lane & 3) == 0) {
                    int pcol = blockIdx.y * 4 + wn;
                    g_pm[(size_t)row * PN_ + pcol] = rm;
                    g_ps[(size_t)row * PN_ + pcol] = rs;
                }
            }
        }
    }
}

// ---------------- causal attention (fp32, online softmax, work-balanced) ----
__global__ __launch_bounds__(128) void attn_kernel() {
    __shared__ float kv[64][64];
    __shared__ float sc[64][128];
    const int z   = blockIdx.y;
    const int b   = z >> 4;
    const int hh  = z & 15;
    const int tid = threadIdx.x;
    const int ntiles = T_ / 128;               // 8

#pragma unroll
    for (int half = 0; half < 2; half++) {
        const int bx = half == 0 ? (ntiles - 1 - blockIdx.x) : blockIdx.x;
        const int t  = bx * 128 + tid;

        const float4* qp = (const float4*)(g_qkv + (size_t)(b * T_ + t) * QKV3 + hh * HS_);
        float q[64];
#pragma unroll
        for (int d4 = 0; d4 < 16; d4++) {
            float4 qq = qp[d4];
            q[d4 * 4 + 0] = qq.x * 8.0f;
            q[d4 * 4 + 1] = qq.y * 8.0f;
            q[d4 * 4 + 2] = qq.z * 8.0f;
            q[d4 * 4 + 3] = qq.w * 8.0f;
        }

        float acc[64];
#pragma unroll
        for (int d = 0; d < 64; d++) acc[d] = 0.f;
        float m = -INFINITY, l = 0.f;

        const int smax = bx * 128 + 127;
        for (int s0 = 0; s0 <= smax; s0 += 64) {
            const float* kbase = g_qkv + (size_t)(b * T_ + s0) * QKV3 + D_ + hh * HS_;
#pragma unroll
            for (int i = 0; i < 8; i++) {
                int lin = tid + 128 * i;
                int row = lin >> 4, c4 = lin & 15;
                *(float4*)&kv[row][c4 * 4] =
                    *(const float4*)(kbase + (size_t)row * QKV3 + c4 * 4);
            }
            __syncthreads();

            int cnt = t - s0 + 1;
            cnt = cnt < 0 ? 0 : (cnt > 64 ? 64 : cnt);
            for (int j = 0; j < cnt; j++) {
                const float4* kr = (const float4*)kv[j];
                float s = 0.f;
#pragma unroll
                for (int d4 = 0; d4 < 16; d4++) {
                    float4 kk = kr[d4];
                    s = fmaf(q[d4 * 4 + 0], kk.x, s);
                    s = fmaf(q[d4 * 4 + 1], kk.y, s);
                    s = fmaf(q[d4 * 4 + 2], kk.z, s);
                    s = fmaf(q[d4 * 4 + 3], kk.w, s);
                }
                sc[j][tid] = s;
            }
            __syncthreads();

            const float* vbase = g_qkv + (size_t)(b * T_ + s0) * QKV3 + 2 * D_ + hh * HS_;
#pragma unroll
            for (int i = 0; i < 8; i++) {
                int lin = tid + 128 * i;
                int row = lin >> 4, c4 = lin & 15;
                *(float4*)&kv[row][c4 * 4] =
                    *(const float4*)(vbase + (size_t)row * QKV3 + c4 * 4);
            }
            __syncthreads();

            if (cnt > 0) {
                float tmax = -INFINITY;
                for (int j = 0; j < cnt; j++) tmax = fmaxf(tmax, sc[j][tid]);
                float mn = fmaxf(m, tmax);
                float scale = __expf(m - mn);
                l *= scale;
#pragma unroll
                for (int d = 0; d < 64; d++) acc[d] *= scale;
                for (int j = 0; j < cnt; j++) {
                    float p = __expf(sc[j][tid] - mn);
                    l += p;
                    const float4* vr = (const float4*)kv[j];
#pragma unroll
                    for (int d4 = 0; d4 < 16; d4++) {
                        float4 vv4 = vr[d4];
                        acc[d4 * 4 + 0] = fmaf(p, vv4.x, acc[d4 * 4 + 0]);
                        acc[d4 * 4 + 1] = fmaf(p, vv4.y, acc[d4 * 4 + 1]);
                        acc[d4 * 4 + 2] = fmaf(p, vv4.z, acc[d4 * 4 + 2]);
                        acc[d4 * 4 + 3] = fmaf(p, vv4.w, acc[d4 * 4 + 3]);
                    }
                }
                m = mn;
            }
            __syncthreads();
        }

        float inv = 1.f / l;
        size_t obase = (size_t)(b * T_ + t) * D_ + hh * HS_;
#pragma unroll
        for (int d = 0; d < 64; d += 2) {
            float v0 = acc[d] * inv, v1 = acc[d + 1] * inv;
            *(__half2*)(g_oh + obase + d) =
                __halves2half2(__float2half(v0), __float2half(v1));
        }
        __syncthreads();
    }
}

// ---------------- loss from LSE partials -------------------------------------
__global__ __launch_bounds__(256) void loss_partial_kernel(const float* __restrict__ logits,
                                                           const int* __restrict__ y) {
    __shared__ float sm_m[256], sm_s[256];
    int row = blockIdx.x;
    int tid = threadIdx.x;
    float m = -INFINITY, s = 0.f;
    for (int i = tid; i < PN_; i += 256) {
        float m2 = g_pm[(size_t)row * PN_ + i];
        float s2 = g_ps[(size_t)row * PN_ + i];
        float mn = fmaxf(m, m2);
        s = s * fast_exp(m - mn) + s2 * fast_exp(m2 - mn);
        m = mn;
    }
    sm_m[tid] = m; sm_s[tid] = s;
    __syncthreads();
    for (int k = 128; k > 0; k >>= 1) {
        if (tid < k) {
            float m2 = sm_m[tid + k], s2 = sm_s[tid + k];
            float mn = fmaxf(sm_m[tid], m2);
            sm_s[tid] = sm_s[tid] * fast_exp(sm_m[tid] - mn) + s2 * fast_exp(m2 - mn);
            sm_m[tid] = mn;
        }
        __syncthreads();
    }
    if (tid == 0) {
        g_loss[row] = sm_m[0] + logf(sm_s[0]) - logits[(size_t)row * V_ + y[row]];
    }
}

__global__ __launch_bounds__(256) void loss_mean_kernel(float* out) {
    __shared__ float red[256];
    int tid = threadIdx.x;
    float s = 0.f;
    for (int i = tid; i < BT_; i += 256) s += g_loss[i];
    red[tid] = s;
    __syncthreads();
    for (int k = 128; k > 0; k >>= 1) {
        if (tid < k) red[tid] += red[tid + k];
        __syncthreads();
    }
    if (tid == 0) *out = red[0] / (float)BT_;
}

// ---------------- launch ----------------------------------------------------
extern "C" void kernel_launch(void* const* d_in, const int* in_sizes, int n_in,
                              void* d_out, int out_size) {
    const int*   x   = (const int*)d_in[0];
    const int*   y   = (const int*)d_in[1];
    const float* tok = (const float*)d_in[2];
    const float* pos = (const float*)d_in[3];
    const float* Wq  = (const float*)d_in[4];
    const float* Wk  = (const float*)d_in[5];
    const float* Wv  = (const float*)d_in[6];
    const float* ffw = (const float*)d_in[7];
    const float* ffb = (const float*)d_in[8];
    const float* fcw = (const float*)d_in[9];
    const float* fcb = (const float*)d_in[10];
    float* out = (float*)d_out;

    __half *phh, *poh, *pfh, *pwqh, *pwfh, *pwch;
    float *pqkv;
    cudaGetSymbolAddress((void**)&phh, g_hh);
    cudaGetSymbolAddress((void**)&poh, g_oh);
    cudaGetSymbolAddress((void**)&pfh, g_fh);
    cudaGetSymbolAddress((void**)&pwqh, g_wqkvh);
    cudaGetSymbolAddress((void**)&pwfh, g_wfh);
    cudaGetSymbolAddress((void**)&pwch, g_wch);
    cudaGetSymbolAddress((void**)&pqkv, g_qkv);

    const int smem1 = 2 * (ATILE + BTILE) * 2;   // 37888 B
    cudaFuncSetAttribute(mma_gemm<0,0,0,0>, cudaFuncAttributeMaxDynamicSharedMemorySize, smem1);
    cudaFuncSetAttribute(mma_gemm<1,1,2,0>, cudaFuncAttributeMaxDynamicSharedMemorySize, smem1);
    cudaFuncSetAttribute(mma_gemm<1,0,0,1>, cudaFuncAttributeMaxDynamicSharedMemorySize, smem1);

    // embedding
    embed_split<<<(BT_ * E_ / 4) / 256, 256>>>(x, tok, pos);

    // weight converts (elementwise, no transpose)
    wconv_qkv<<<(H_*E_*HS_/4)/256, 256>>>(Wq, pwqh);
    wconv_qkv<<<(H_*E_*HS_/4)/256, 256>>>(Wk, pwqh + D_);
    wconv_qkv<<<(H_*E_*HS_/4)/256, 256>>>(Wv, pwqh + 2*D_);
    wconv<<<(D_*D_/4)/256, 256>>>(ffw, pwfh);
    wconv<<<((size_t)D_*V_/4)/256, 256>>>(fcw, pwch);

    // fused QKV GEMM: [4096,3072] = h @ Wqkv[k][n]  (1-pass fp16)
    mma_gemm<0,0,0,0><<<dim3(BT_/128, QKV3/128), 256, smem1>>>(
        phh, pwqh, nullptr, pqkv, nullptr, BT_, QKV3, E_);

    // attention (work-balanced tile pairs)
    attn_kernel<<<dim3(T_/256, B_*H_), 128>>>();

    // FF: relu(o @ ff_w + ff_b) -> fp16 (1-pass)
    mma_gemm<1,1,2,0><<<dim3(BT_/128, D_/128), 256, smem1>>>(
        poh, pwfh, ffb, nullptr, pfh, BT_, D_, D_);

    // logits: ff @ fc_w + fc_b -> d_out fp32 (1-pass, fused LSE partials)
    mma_gemm<1,0,0,1><<<dim3(BT_/128, V_/128), 256, smem1>>>(
        pfh, pwch, fcb, out, nullptr, BT_, V_, D_);

    // loss
    loss_partial_kernel<<<BT_, 256>>>(out, y);
    long long logits_elems = (long long)BT_ * V_;
    if ((long long)out_size > logits_elems) {
        loss_mean_kernel<<<1, 256>>>(out + (size_t)logits_elems);
    }
}